// round 10
// baseline (speedup 1.0000x reference)
#include <cuda_runtime.h>
#include <cuda_fp16.h>
#include <math.h>

// ---------------------------------------------------------------------------
// out = gelu_tanh(x) * gate(row)
// gate = exp(-tau*cos) * (1 + w*relu(tanh(sigma*mean|z|) - surp_ema))
// x [4,4096,2048] fp32 -> 16384 rows, D=2048.
// CTA: 256 threads, 8 cols/thread (2x float4), 8 rows/CTA, depth-1 prefetch.
// Channel stats in REGISTERS: is/nm as half2 (8 regs), en fp32 (8 regs).
// Warp sums via shfl butterfly (redux.f32 unsupported on sm_103).
// One barrier per row; every warp computes the gate redundantly.
// ---------------------------------------------------------------------------

#define R_PER_CTA 8

__device__ __forceinline__ float ex2f(float v) {
    float y; asm("ex2.approx.f32 %0, %1;" : "=f"(y) : "f"(v)); return y;
}
__device__ __forceinline__ float rcpf(float v) {
    float y; asm("rcp.approx.f32 %0, %1;" : "=f"(y) : "f"(v)); return y;
}
__device__ __forceinline__ float tanhf_hw(float v) {
    float y; asm("tanh.approx.f32 %0, %1;" : "=f"(y) : "f"(v)); return y;
}
__device__ __forceinline__ float softplus_f(float v) {
    return (v > 20.0f) ? v : log1pf(expf(v));
}
__device__ __forceinline__ float warp_sum(float v) {
    #pragma unroll
    for (int o = 16; o > 0; o >>= 1)
        v += __shfl_xor_sync(0xffffffffu, v, o);
    return v;
}

// gelu = 0.5x + 0.5x * tanh(x*(C1 + C2*x^2))
__device__ __forceinline__ float gelu_hw(float x) {
    const float C1 = 0.7978845608f;   // sqrt(2/pi)
    const float C2 = 0.0356774081f;   // C1 * 0.044715
    float u = x * fmaf(x * x, C2, C1);
    float t = tanhf_hw(u);
    float h = 0.5f * x;
    return fmaf(h, t, h);
}

__global__ __launch_bounds__(256, 4)
void fused_gelu_gate(const float* __restrict__ x,
                     const float* __restrict__ ema_mean,
                     const float* __restrict__ ema_sq,
                     const float* __restrict__ ema_out,
                     const float* __restrict__ surp_ema,
                     const float* __restrict__ log_tau,
                     const float* __restrict__ log_sigma,
                     const float* __restrict__ log_w,
                     float* __restrict__ out) {
    const int D = 2048;
    const int tid = threadIdx.x;
    const int wid = tid >> 5;
    const int lid = tid & 31;
    const int i0 = tid;          // float4 index 0..255
    const int i1 = tid + 256;    // float4 index 256..511

    __shared__ float4 red[2][8];

    // ---- prologue: channel stats into REGISTERS ----
    __half2 isA0, isA1, isB0, isB1;   // 1/(std+eps), chunks A(i0) and B(i1)
    __half2 nmA0, nmA1, nmB0, nmB1;   // -mu*is
    float4 enA, enB;                   // ema_out (normalized below)
    {
        const float4* M4 = (const float4*)ema_mean;
        const float4* Q4 = (const float4*)ema_sq;
        const float4* E4 = (const float4*)ema_out;

        float4 mA = M4[i0], mB = M4[i1];
        float4 qA = Q4[i0], qB = Q4[i1];
        enA = E4[i0]; enB = E4[i1];

        float iv[8], nv[8];
        float mm[8] = {mA.x, mA.y, mA.z, mA.w, mB.x, mB.y, mB.z, mB.w};
        float qq[8] = {qA.x, qA.y, qA.z, qA.w, qB.x, qB.y, qB.z, qB.w};
        #pragma unroll
        for (int j = 0; j < 8; j++) {
            float var = fmaxf(qq[j] - mm[j] * mm[j], 1e-4f);
            float s = rcpf(sqrtf(var) + 1e-5f);
            iv[j] = s;
            nv[j] = -mm[j] * s;
        }
        isA0 = __floats2half2_rn(iv[0], iv[1]);
        isA1 = __floats2half2_rn(iv[2], iv[3]);
        isB0 = __floats2half2_rn(iv[4], iv[5]);
        isB1 = __floats2half2_rn(iv[6], iv[7]);
        nmA0 = __floats2half2_rn(nv[0], nv[1]);
        nmA1 = __floats2half2_rn(nv[2], nv[3]);
        nmB0 = __floats2half2_rn(nv[4], nv[5]);
        nmB1 = __floats2half2_rn(nv[6], nv[7]);

        float ess = 0.0f;
        ess = fmaf(enA.x, enA.x, ess);
        ess = fmaf(enA.y, enA.y, ess);
        ess = fmaf(enA.z, enA.z, ess);
        ess = fmaf(enA.w, enA.w, ess);
        ess = fmaf(enB.x, enB.x, ess);
        ess = fmaf(enB.y, enB.y, ess);
        ess = fmaf(enB.z, enB.z, ess);
        ess = fmaf(enB.w, enB.w, ess);

        ess = warp_sum(ess);
        if (lid == 0) red[0][wid] = make_float4(ess, 0.f, 0.f, 0.f);
        __syncthreads();
        float v = red[0][lid & 7].x;
        #pragma unroll
        for (int o = 1; o < 8; o <<= 1) v += __shfl_xor_sync(0xffffffffu, v, o);
        float inv_norm = rcpf(fmaxf(sqrtf(v), 1e-12f));
        enA.x *= inv_norm; enA.y *= inv_norm; enA.z *= inv_norm; enA.w *= inv_norm;
        enB.x *= inv_norm; enB.y *= inv_norm; enB.z *= inv_norm; enB.w *= inv_norm;
        __syncthreads();   // red[] reused in row loop
    }

    // ---- scalars (redundant per thread, broadcast loads) ----
    const float ntl = -expf(log_tau[0]) * 1.44269504f;   // -tau*log2(e)
    const float sg  = softplus_f(log_sigma[0]);
    const float w   = softplus_f(log_w[0]);
    const float sp  = surp_ema[0];

    // ---- row loop: depth-1 prefetch, ONE barrier per row ----
    long long row0 = (long long)blockIdx.x * R_PER_CTA;
    const float4* xbase4 = (const float4*)(x + row0 * D);
    float4*       obase4 = (float4*)(out + row0 * D);

    float4 ca = __ldcs(xbase4 + i0);
    float4 cb = __ldcs(xbase4 + i1);

    #pragma unroll 1
    for (int r = 0; r < R_PER_CTA; r++) {
        float4 na, nb;
        if (r < R_PER_CTA - 1) {
            const float4* xrn = xbase4 + (long long)(r + 1) * 512;
            na = __ldcs(xrn + i0);
            nb = __ldcs(xrn + i1);
        }

        // |z| sums in half2 (register stats)
        __half2 az_h = __float2half2_rn(0.0f);
        {
            __half2 xh0 = __floats2half2_rn(ca.x, ca.y);
            __half2 xh1 = __floats2half2_rn(ca.z, ca.w);
            __half2 xh2 = __floats2half2_rn(cb.x, cb.y);
            __half2 xh3 = __floats2half2_rn(cb.z, cb.w);
            az_h = __hadd2(az_h, __habs2(__hfma2(xh0, isA0, nmA0)));
            az_h = __hadd2(az_h, __habs2(__hfma2(xh1, isA1, nmA1)));
            az_h = __hadd2(az_h, __habs2(__hfma2(xh2, isB0, nmB0)));
            az_h = __hadd2(az_h, __habs2(__hfma2(xh3, isB1, nmB1)));
        }
        float2 azf = __half22float2(az_h);
        float az = azf.x + azf.y;

        // gelu in place + sq/dot sums (fp32)
        float sq = 0.f, dt = 0.f;
        {
            float* pa = &ca.x;
            const float* peA = &enA.x;
            #pragma unroll
            for (int j = 0; j < 4; j++) {
                float o = gelu_hw(pa[j]);
                pa[j] = o;
                sq = fmaf(o, o, sq);
                dt = fmaf(o, peA[j], dt);
            }
            float* pb = &cb.x;
            const float* peB = &enB.x;
            #pragma unroll
            for (int j = 0; j < 4; j++) {
                float o = gelu_hw(pb[j]);
                pb[j] = o;
                sq = fmaf(o, o, sq);
                dt = fmaf(o, peB[j], dt);
            }
        }

        az = warp_sum(az);
        sq = warp_sum(sq);
        dt = warp_sum(dt);
        if (lid == 0) red[r & 1][wid] = make_float4(az, sq, dt, 0.f);
        __syncthreads();

        // every warp reduces the 8 partials + computes gate (no 2nd barrier)
        float4 v = red[r & 1][lid & 7];
        #pragma unroll
        for (int o = 1; o < 8; o <<= 1) {
            v.x += __shfl_xor_sync(0xffffffffu, v.x, o);
            v.y += __shfl_xor_sync(0xffffffffu, v.y, o);
            v.z += __shfl_xor_sync(0xffffffffu, v.z, o);
        }
        float surp_mod = fmaxf(tanhf_hw(sg * (v.x * (1.0f / 2048.0f))) - sp, 0.0f);
        float cs = v.z * rsqrtf(fmaxf(v.y, 1e-24f));
        cs = fminf(fmaxf(cs, -1.0f), 1.0f);
        float gate = ex2f(ntl * cs) * fmaf(w, surp_mod, 1.0f);

        float4* orow = obase4 + (long long)r * 512;
        float4 o0 = {ca.x * gate, ca.y * gate, ca.z * gate, ca.w * gate};
        float4 o1 = {cb.x * gate, cb.y * gate, cb.z * gate, cb.w * gate};
        __stcs(orow + i0, o0);
        __stcs(orow + i1, o1);

        ca = na; cb = nb;
    }
}

extern "C" void kernel_launch(void* const* d_in, const int* in_sizes, int n_in,
                              void* d_out, int out_size) {
    const float* x        = (const float*)d_in[0];
    const float* ema_mean = (const float*)d_in[1];
    const float* ema_sq   = (const float*)d_in[2];
    const float* ema_out  = (const float*)d_in[3];
    const float* surp_ema = (const float*)d_in[4];
    const float* log_tau  = (const float*)d_in[5];
    const float* log_sig  = (const float*)d_in[6];
    const float* log_w    = (const float*)d_in[7];
    float* out = (float*)d_out;

    int D = in_sizes[1];                       // 2048
    long long total = (long long)in_sizes[0];  // 33554432
    int rows = (int)(total / D);               // 16384
    int grid = rows / R_PER_CTA;               // 2048

    fused_gelu_gate<<<grid, 256>>>(x, ema_mean, ema_sq, ema_out, surp_ema,
                                   log_tau, log_sig, log_w, out);
}

// round 12
// speedup vs baseline: 1.0863x; 1.0863x over previous
#include <cuda_runtime.h>
#include <cuda_fp16.h>
#include <cstdint>
#include <math.h>

// ---------------------------------------------------------------------------
// out = gelu_tanh(x) * gate(row)
// gate = exp(-tau*cos) * (1 + w*relu(tanh(sigma*mean|z|) - surp_ema))
// x [4,4096,2048] fp32 -> 16384 rows, D=2048.
// CTA: 256 threads, 8 cols/thread, 8 rows/CTA.
// cp.async.cg 3-deep SMEM row ring for x (deep MLP without registers).
// Channel stats in registers (is/nm half2, en fp32). One barrier per row.
// ---------------------------------------------------------------------------

#define R_PER_CTA 8
#define DEPTH 3

__device__ __forceinline__ float ex2f(float v) {
    float y; asm("ex2.approx.f32 %0, %1;" : "=f"(y) : "f"(v)); return y;
}
__device__ __forceinline__ float rcpf(float v) {
    float y; asm("rcp.approx.f32 %0, %1;" : "=f"(y) : "f"(v)); return y;
}
__device__ __forceinline__ float tanhf_hw(float v) {
    float y; asm("tanh.approx.f32 %0, %1;" : "=f"(y) : "f"(v)); return y;
}
__device__ __forceinline__ float softplus_f(float v) {
    return (v > 20.0f) ? v : log1pf(expf(v));
}
__device__ __forceinline__ float warp_sum(float v) {
    #pragma unroll
    for (int o = 16; o > 0; o >>= 1)
        v += __shfl_xor_sync(0xffffffffu, v, o);
    return v;
}
__device__ __forceinline__ unsigned smem_u32(const void* p) {
    unsigned a;
    asm("{ .reg .u64 t; cvta.to.shared.u64 t, %1; cvt.u32.u64 %0, t; }"
        : "=r"(a) : "l"(p));
    return a;
}
__device__ __forceinline__ void cp_async16(unsigned dst, const void* src) {
    asm volatile("cp.async.cg.shared.global [%0], [%1], 16;"
                 :: "r"(dst), "l"(src) : "memory");
}
__device__ __forceinline__ void cp_commit() {
    asm volatile("cp.async.commit_group;" ::: "memory");
}
__device__ __forceinline__ void cp_wait2() {
    asm volatile("cp.async.wait_group 2;" ::: "memory");
}

// gelu = 0.5x + 0.5x * tanh(x*(C1 + C2*x^2))
__device__ __forceinline__ float gelu_hw(float x) {
    const float C1 = 0.7978845608f;   // sqrt(2/pi)
    const float C2 = 0.0356774081f;   // C1 * 0.044715
    float u = x * fmaf(x * x, C2, C1);
    float t = tanhf_hw(u);
    float h = 0.5f * x;
    return fmaf(h, t, h);
}

__global__ __launch_bounds__(256, 4)
void fused_gelu_gate(const float* __restrict__ x,
                     const float* __restrict__ ema_mean,
                     const float* __restrict__ ema_sq,
                     const float* __restrict__ ema_out,
                     const float* __restrict__ surp_ema,
                     const float* __restrict__ log_tau,
                     const float* __restrict__ log_sigma,
                     const float* __restrict__ log_w,
                     float* __restrict__ out) {
    const int D = 2048;
    const int tid = threadIdx.x;
    const int wid = tid >> 5;
    const int lid = tid & 31;
    const int i0 = tid;          // float4 index 0..255
    const int i1 = tid + 256;    // float4 index 256..511

    __shared__ float xbuf[DEPTH * 2048];
    __shared__ float4 red[2][8];

    const float4* XB4 = (const float4*)xbuf;
    const unsigned xb_a = smem_u32(xbuf);
    const unsigned d0 = tid * 16;         // byte offset for chunk 0
    const unsigned d1 = tid * 16 + 4096;  // byte offset for chunk 1

    long long row0 = (long long)blockIdx.x * R_PER_CTA;
    const float4* xbase4 = (const float4*)(x + row0 * D);
    float4*       obase4 = (float4*)(out + row0 * D);

    // ---- kick off the async pipeline FIRST (hide latency behind prologue) --
    #pragma unroll
    for (int p = 0; p < DEPTH; p++) {
        const float4* xr = xbase4 + (long long)p * 512;
        unsigned base = xb_a + p * 8192;
        cp_async16(base + d0, xr + i0);
        cp_async16(base + d1, xr + i1);
        cp_commit();
    }

    // ---- prologue: channel stats into REGISTERS ----
    __half2 isA0, isA1, isB0, isB1;
    __half2 nmA0, nmA1, nmB0, nmB1;
    float4 enA, enB;
    {
        const float4* M4 = (const float4*)ema_mean;
        const float4* Q4 = (const float4*)ema_sq;
        const float4* E4 = (const float4*)ema_out;

        float4 mA = M4[i0], mB = M4[i1];
        float4 qA = Q4[i0], qB = Q4[i1];
        enA = E4[i0]; enB = E4[i1];

        float iv[8], nv[8];
        float mm[8] = {mA.x, mA.y, mA.z, mA.w, mB.x, mB.y, mB.z, mB.w};
        float qq[8] = {qA.x, qA.y, qA.z, qA.w, qB.x, qB.y, qB.z, qB.w};
        #pragma unroll
        for (int j = 0; j < 8; j++) {
            float var = fmaxf(qq[j] - mm[j] * mm[j], 1e-4f);
            float s = rcpf(sqrtf(var) + 1e-5f);
            iv[j] = s;
            nv[j] = -mm[j] * s;
        }
        isA0 = __floats2half2_rn(iv[0], iv[1]);
        isA1 = __floats2half2_rn(iv[2], iv[3]);
        isB0 = __floats2half2_rn(iv[4], iv[5]);
        isB1 = __floats2half2_rn(iv[6], iv[7]);
        nmA0 = __floats2half2_rn(nv[0], nv[1]);
        nmA1 = __floats2half2_rn(nv[2], nv[3]);
        nmB0 = __floats2half2_rn(nv[4], nv[5]);
        nmB1 = __floats2half2_rn(nv[6], nv[7]);

        float ess = 0.0f;
        ess = fmaf(enA.x, enA.x, ess); ess = fmaf(enA.y, enA.y, ess);
        ess = fmaf(enA.z, enA.z, ess); ess = fmaf(enA.w, enA.w, ess);
        ess = fmaf(enB.x, enB.x, ess); ess = fmaf(enB.y, enB.y, ess);
        ess = fmaf(enB.z, enB.z, ess); ess = fmaf(enB.w, enB.w, ess);

        ess = warp_sum(ess);
        if (lid == 0) red[0][wid] = make_float4(ess, 0.f, 0.f, 0.f);
        __syncthreads();
        float v = red[0][lid & 7].x;
        #pragma unroll
        for (int o = 1; o < 8; o <<= 1) v += __shfl_xor_sync(0xffffffffu, v, o);
        float inv_norm = rcpf(fmaxf(sqrtf(v), 1e-12f));
        enA.x *= inv_norm; enA.y *= inv_norm; enA.z *= inv_norm; enA.w *= inv_norm;
        enB.x *= inv_norm; enB.y *= inv_norm; enB.z *= inv_norm; enB.w *= inv_norm;
        __syncthreads();   // red[] reused below
    }

    // ---- scalars ----
    const float ntl = -expf(log_tau[0]) * 1.44269504f;
    const float sg  = softplus_f(log_sigma[0]);
    const float w   = softplus_f(log_w[0]);
    const float sp  = surp_ema[0];

    // ---- row loop ----
    #pragma unroll 1
    for (int r = 0; r < R_PER_CTA; r++) {
        cp_wait2();                       // row r is resident

        const int buf = r % DEPTH;
        float4 ca = XB4[buf * 512 + i0];  // this thread's own copied chunks
        float4 cb = XB4[buf * 512 + i1];

        // refill this buffer slot with row r+DEPTH (same thread, same addrs)
        if (r + DEPTH < R_PER_CTA) {
            const float4* xr = xbase4 + (long long)(r + DEPTH) * 512;
            unsigned base = xb_a + buf * 8192;
            cp_async16(base + d0, xr + i0);
            cp_async16(base + d1, xr + i1);
        }
        cp_commit();                      // always commit (group bookkeeping)

        // |z| sums in half2 (register stats)
        __half2 az_h = __float2half2_rn(0.0f);
        {
            __half2 xh0 = __floats2half2_rn(ca.x, ca.y);
            __half2 xh1 = __floats2half2_rn(ca.z, ca.w);
            __half2 xh2 = __floats2half2_rn(cb.x, cb.y);
            __half2 xh3 = __floats2half2_rn(cb.z, cb.w);
            az_h = __hadd2(az_h, __habs2(__hfma2(xh0, isA0, nmA0)));
            az_h = __hadd2(az_h, __habs2(__hfma2(xh1, isA1, nmA1)));
            az_h = __hadd2(az_h, __habs2(__hfma2(xh2, isB0, nmB0)));
            az_h = __hadd2(az_h, __habs2(__hfma2(xh3, isB1, nmB1)));
        }
        float2 azf = __half22float2(az_h);
        float az = azf.x + azf.y;

        // gelu in place + sq/dot sums (fp32)
        float sq = 0.f, dt = 0.f;
        {
            float* pa = &ca.x;
            const float* peA = &enA.x;
            #pragma unroll
            for (int j = 0; j < 4; j++) {
                float o = gelu_hw(pa[j]);
                pa[j] = o;
                sq = fmaf(o, o, sq);
                dt = fmaf(o, peA[j], dt);
            }
            float* pb = &cb.x;
            const float* peB = &enB.x;
            #pragma unroll
            for (int j = 0; j < 4; j++) {
                float o = gelu_hw(pb[j]);
                pb[j] = o;
                sq = fmaf(o, o, sq);
                dt = fmaf(o, peB[j], dt);
            }
        }

        az = warp_sum(az);
        sq = warp_sum(sq);
        dt = warp_sum(dt);
        if (lid == 0) red[r & 1][wid] = make_float4(az, sq, dt, 0.f);
        __syncthreads();

        // every warp reduces the 8 partials + computes gate (no 2nd barrier)
        float4 v = red[r & 1][lid & 7];
        #pragma unroll
        for (int o = 1; o < 8; o <<= 1) {
            v.x += __shfl_xor_sync(0xffffffffu, v.x, o);
            v.y += __shfl_xor_sync(0xffffffffu, v.y, o);
            v.z += __shfl_xor_sync(0xffffffffu, v.z, o);
        }
        float surp_mod = fmaxf(tanhf_hw(sg * (v.x * (1.0f / 2048.0f))) - sp, 0.0f);
        float cs = v.z * rsqrtf(fmaxf(v.y, 1e-24f));
        cs = fminf(fmaxf(cs, -1.0f), 1.0f);
        float gate = ex2f(ntl * cs) * fmaf(w, surp_mod, 1.0f);

        float4* orow = obase4 + (long long)r * 512;
        float4 o0 = {ca.x * gate, ca.y * gate, ca.z * gate, ca.w * gate};
        float4 o1 = {cb.x * gate, cb.y * gate, cb.z * gate, cb.w * gate};
        __stcs(orow + i0, o0);
        __stcs(orow + i1, o1);
    }
}

extern "C" void kernel_launch(void* const* d_in, const int* in_sizes, int n_in,
                              void* d_out, int out_size) {
    const float* x        = (const float*)d_in[0];
    const float* ema_mean = (const float*)d_in[1];
    const float* ema_sq   = (const float*)d_in[2];
    const float* ema_out  = (const float*)d_in[3];
    const float* surp_ema = (const float*)d_in[4];
    const float* log_tau  = (const float*)d_in[5];
    const float* log_sig  = (const float*)d_in[6];
    const float* log_w    = (const float*)d_in[7];
    float* out = (float*)d_out;

    int D = in_sizes[1];                       // 2048
    long long total = (long long)in_sizes[0];  // 33554432
    int rows = (int)(total / D);               // 16384
    int grid = rows / R_PER_CTA;               // 2048

    fused_gelu_gate<<<grid, 256>>>(x, ema_mean, ema_sq, ema_out, surp_ema,
                                   log_tau, log_sig, log_w, out);
}

// round 13
// speedup vs baseline: 1.0914x; 1.0047x over previous
#include <cuda_runtime.h>
#include <cuda_fp16.h>
#include <cstdint>
#include <math.h>

// ---------------------------------------------------------------------------
// out = gelu_tanh(x) * gate(row)
// gate = exp(-tau*cos) * (1 + w*relu(tanh(sigma*mean|z|) - surp_ema))
// x [4,4096,2048] fp32 -> 16384 rows, D=2048.
// CTA: 256 threads, 8 cols/thread, 16 rows/CTA.
// cp.async.cg 4-deep SMEM row ring (buf = r&3, wait_group 3).
// Channel stats in registers (is/nm half2, en fp32). One barrier per row.
// ---------------------------------------------------------------------------

#define R_PER_CTA 16
#define DEPTH 4

__device__ __forceinline__ float ex2f(float v) {
    float y; asm("ex2.approx.f32 %0, %1;" : "=f"(y) : "f"(v)); return y;
}
__device__ __forceinline__ float rcpf(float v) {
    float y; asm("rcp.approx.f32 %0, %1;" : "=f"(y) : "f"(v)); return y;
}
__device__ __forceinline__ float tanhf_hw(float v) {
    float y; asm("tanh.approx.f32 %0, %1;" : "=f"(y) : "f"(v)); return y;
}
__device__ __forceinline__ float softplus_f(float v) {
    return (v > 20.0f) ? v : log1pf(expf(v));
}
__device__ __forceinline__ float warp_sum(float v) {
    #pragma unroll
    for (int o = 16; o > 0; o >>= 1)
        v += __shfl_xor_sync(0xffffffffu, v, o);
    return v;
}
__device__ __forceinline__ unsigned smem_u32(const void* p) {
    unsigned a;
    asm("{ .reg .u64 t; cvta.to.shared.u64 t, %1; cvt.u32.u64 %0, t; }"
        : "=r"(a) : "l"(p));
    return a;
}
__device__ __forceinline__ void cp_async16(unsigned dst, const void* src) {
    asm volatile("cp.async.cg.shared.global [%0], [%1], 16;"
                 :: "r"(dst), "l"(src) : "memory");
}
__device__ __forceinline__ void cp_commit() {
    asm volatile("cp.async.commit_group;" ::: "memory");
}
__device__ __forceinline__ void cp_wait3() {
    asm volatile("cp.async.wait_group 3;" ::: "memory");
}

// gelu = 0.5x + 0.5x * tanh(x*(C1 + C2*x^2))
__device__ __forceinline__ float gelu_hw(float x) {
    const float C1 = 0.7978845608f;   // sqrt(2/pi)
    const float C2 = 0.0356774081f;   // C1 * 0.044715
    float u = x * fmaf(x * x, C2, C1);
    float t = tanhf_hw(u);
    float h = 0.5f * x;
    return fmaf(h, t, h);
}

__global__ __launch_bounds__(256, 4)
void fused_gelu_gate(const float* __restrict__ x,
                     const float* __restrict__ ema_mean,
                     const float* __restrict__ ema_sq,
                     const float* __restrict__ ema_out,
                     const float* __restrict__ surp_ema,
                     const float* __restrict__ log_tau,
                     const float* __restrict__ log_sigma,
                     const float* __restrict__ log_w,
                     float* __restrict__ out) {
    const int D = 2048;
    const int tid = threadIdx.x;
    const int wid = tid >> 5;
    const int lid = tid & 31;
    const int i0 = tid;          // float4 index 0..255
    const int i1 = tid + 256;    // float4 index 256..511

    __shared__ float xbuf[DEPTH * 2048];
    __shared__ float4 red[2][8];

    const float4* XB4 = (const float4*)xbuf;
    const unsigned xb_a = smem_u32(xbuf);
    const unsigned d0 = xb_a + tid * 16;         // smem dst chunk 0
    const unsigned d1 = xb_a + tid * 16 + 4096;  // smem dst chunk 1

    long long row0 = (long long)blockIdx.x * R_PER_CTA;
    const float4* xbase4 = (const float4*)(x + row0 * D);
    float4*       obase4 = (float4*)(out + row0 * D);

    // per-thread global source pointers (advance by 512 float4 per row)
    const float4* src0 = xbase4 + i0;
    const float4* src1 = xbase4 + i1;

    // ---- kick off async pipeline FIRST (latency hidden behind prologue) ----
    #pragma unroll
    for (int p = 0; p < DEPTH; p++) {
        cp_async16(d0 + p * 8192u, src0 + (long long)p * 512);
        cp_async16(d1 + p * 8192u, src1 + (long long)p * 512);
        cp_commit();
    }

    // ---- prologue: channel stats into REGISTERS ----
    __half2 isA0, isA1, isB0, isB1;
    __half2 nmA0, nmA1, nmB0, nmB1;
    float4 enA, enB;
    {
        const float4* M4 = (const float4*)ema_mean;
        const float4* Q4 = (const float4*)ema_sq;
        const float4* E4 = (const float4*)ema_out;

        float4 mA = M4[i0], mB = M4[i1];
        float4 qA = Q4[i0], qB = Q4[i1];
        enA = E4[i0]; enB = E4[i1];

        float iv[8], nv[8];
        float mm[8] = {mA.x, mA.y, mA.z, mA.w, mB.x, mB.y, mB.z, mB.w};
        float qq[8] = {qA.x, qA.y, qA.z, qA.w, qB.x, qB.y, qB.z, qB.w};
        #pragma unroll
        for (int j = 0; j < 8; j++) {
            float var = fmaxf(qq[j] - mm[j] * mm[j], 1e-4f);
            float s = rcpf(sqrtf(var) + 1e-5f);
            iv[j] = s;
            nv[j] = -mm[j] * s;
        }
        isA0 = __floats2half2_rn(iv[0], iv[1]);
        isA1 = __floats2half2_rn(iv[2], iv[3]);
        isB0 = __floats2half2_rn(iv[4], iv[5]);
        isB1 = __floats2half2_rn(iv[6], iv[7]);
        nmA0 = __floats2half2_rn(nv[0], nv[1]);
        nmA1 = __floats2half2_rn(nv[2], nv[3]);
        nmB0 = __floats2half2_rn(nv[4], nv[5]);
        nmB1 = __floats2half2_rn(nv[6], nv[7]);

        float ess = 0.0f;
        ess = fmaf(enA.x, enA.x, ess); ess = fmaf(enA.y, enA.y, ess);
        ess = fmaf(enA.z, enA.z, ess); ess = fmaf(enA.w, enA.w, ess);
        ess = fmaf(enB.x, enB.x, ess); ess = fmaf(enB.y, enB.y, ess);
        ess = fmaf(enB.z, enB.z, ess); ess = fmaf(enB.w, enB.w, ess);

        ess = warp_sum(ess);
        if (lid == 0) red[0][wid] = make_float4(ess, 0.f, 0.f, 0.f);
        __syncthreads();
        float v = red[0][lid & 7].x;
        #pragma unroll
        for (int o = 1; o < 8; o <<= 1) v += __shfl_xor_sync(0xffffffffu, v, o);
        float inv_norm = rcpf(fmaxf(sqrtf(v), 1e-12f));
        enA.x *= inv_norm; enA.y *= inv_norm; enA.z *= inv_norm; enA.w *= inv_norm;
        enB.x *= inv_norm; enB.y *= inv_norm; enB.z *= inv_norm; enB.w *= inv_norm;
        __syncthreads();   // red[] reused below
    }

    // ---- scalars ----
    const float ntl = -expf(log_tau[0]) * 1.44269504f;
    const float sg  = softplus_f(log_sigma[0]);
    const float w   = softplus_f(log_w[0]);
    const float sp  = surp_ema[0];

    // ---- row loop ----
    #pragma unroll 1
    for (int r = 0; r < R_PER_CTA; r++) {
        cp_wait3();                       // row r resident (3 groups pending)

        const int buf = r & (DEPTH - 1);
        float4 ca = XB4[buf * 512 + i0];  // this thread's own copied chunks
        float4 cb = XB4[buf * 512 + i1];

        // refill this slot with row r+DEPTH (same thread, same addresses)
        if (r + DEPTH < R_PER_CTA) {
            cp_async16(d0 + buf * 8192u, src0 + (long long)(r + DEPTH) * 512);
            cp_async16(d1 + buf * 8192u, src1 + (long long)(r + DEPTH) * 512);
        }
        cp_commit();                      // always commit (group bookkeeping)

        // |z| sums in half2 (register stats)
        __half2 az_h = __float2half2_rn(0.0f);
        {
            __half2 xh0 = __floats2half2_rn(ca.x, ca.y);
            __half2 xh1 = __floats2half2_rn(ca.z, ca.w);
            __half2 xh2 = __floats2half2_rn(cb.x, cb.y);
            __half2 xh3 = __floats2half2_rn(cb.z, cb.w);
            az_h = __hadd2(az_h, __habs2(__hfma2(xh0, isA0, nmA0)));
            az_h = __hadd2(az_h, __habs2(__hfma2(xh1, isA1, nmA1)));
            az_h = __hadd2(az_h, __habs2(__hfma2(xh2, isB0, nmB0)));
            az_h = __hadd2(az_h, __habs2(__hfma2(xh3, isB1, nmB1)));
        }
        float2 azf = __half22float2(az_h);
        float az = azf.x + azf.y;

        // gelu in place + sq/dot sums (fp32)
        float sq = 0.f, dt = 0.f;
        {
            float* pa = &ca.x;
            const float* peA = &enA.x;
            #pragma unroll
            for (int j = 0; j < 4; j++) {
                float o = gelu_hw(pa[j]);
                pa[j] = o;
                sq = fmaf(o, o, sq);
                dt = fmaf(o, peA[j], dt);
            }
            float* pb = &cb.x;
            const float* peB = &enB.x;
            #pragma unroll
            for (int j = 0; j < 4; j++) {
                float o = gelu_hw(pb[j]);
                pb[j] = o;
                sq = fmaf(o, o, sq);
                dt = fmaf(o, peB[j], dt);
            }
        }

        az = warp_sum(az);
        sq = warp_sum(sq);
        dt = warp_sum(dt);
        if (lid == 0) red[r & 1][wid] = make_float4(az, sq, dt, 0.f);
        __syncthreads();

        // every warp reduces the 8 partials + computes gate (no 2nd barrier)
        float4 v = red[r & 1][lid & 7];
        #pragma unroll
        for (int o = 1; o < 8; o <<= 1) {
            v.x += __shfl_xor_sync(0xffffffffu, v.x, o);
            v.y += __shfl_xor_sync(0xffffffffu, v.y, o);
            v.z += __shfl_xor_sync(0xffffffffu, v.z, o);
        }
        float surp_mod = fmaxf(tanhf_hw(sg * (v.x * (1.0f / 2048.0f))) - sp, 0.0f);
        float cs = v.z * rsqrtf(fmaxf(v.y, 1e-24f));
        cs = fminf(fmaxf(cs, -1.0f), 1.0f);
        float gate = ex2f(ntl * cs) * fmaf(w, surp_mod, 1.0f);

        float4* orow = obase4 + (long long)r * 512;
        float4 o0 = {ca.x * gate, ca.y * gate, ca.z * gate, ca.w * gate};
        float4 o1 = {cb.x * gate, cb.y * gate, cb.z * gate, cb.w * gate};
        __stcs(orow + i0, o0);
        __stcs(orow + i1, o1);
    }
}

extern "C" void kernel_launch(void* const* d_in, const int* in_sizes, int n_in,
                              void* d_out, int out_size) {
    const float* x        = (const float*)d_in[0];
    const float* ema_mean = (const float*)d_in[1];
    const float* ema_sq   = (const float*)d_in[2];
    const float* ema_out  = (const float*)d_in[3];
    const float* surp_ema = (const float*)d_in[4];
    const float* log_tau  = (const float*)d_in[5];
    const float* log_sig  = (const float*)d_in[6];
    const float* log_w    = (const float*)d_in[7];
    float* out = (float*)d_out;

    int D = in_sizes[1];                       // 2048
    long long total = (long long)in_sizes[0];  // 33554432
    int rows = (int)(total / D);               // 16384
    int grid = rows / R_PER_CTA;               // 1024

    fused_gelu_gate<<<grid, 256>>>(x, ema_mean, ema_sq, ema_out, surp_ema,
                                   log_tau, log_sig, log_w, out);
}